// round 13
// baseline (speedup 1.0000x reference)
#include <cuda_runtime.h>
#include <math_constants.h>

#define D_FEAT   128
#define K_NEIGH  32
#define WARPS_PER_CTA 4

// One WARP per batch item, no shared memory (R9 structure — proven best at
// the practical LTS bandwidth cap; 56-reg / 9-CTA config is the measured
// concurrency optimum: 48reg->L2 55%, 56reg->64.4%, 80reg->60%).
// Sim: 4 rows per pass, 8-lane groups with 128B-contiguous chunks; owner
// permutation lane 8g+p <- row 4p+g (no route shuffle). Exact-sim ties only
// arise from duplicate neighbor indices (identical rows), so owner-order
// tie-break is output-equivalent to jax.lax.top_k row-order.
// Key = dot * rsqrt(||n||^2) (center norm cancels for top-k).
// Selection (new vs R9): single-pass rank via 32 INDEPENDENT broadcast
// shuffles (replaces the ~450-cycle serial REDUX chain):
//   rank_i = #{j: s_j > s_i} + #{j<i: s_j == s_i}
// Ranks are a permutation of 0..31, so ballot(rank < ns) has exactly ns bits.
// Winner rows then resolved and gathered back-to-back (MLP=ns, L1/L2-hot).
__global__ __launch_bounds__(WARPS_PER_CTA * 32, 9)
void intra_agg_kernel(const float*  __restrict__ feats,
                      const int*    __restrict__ nodes,
                      const int*    __restrict__ neighs,
                      const int*    __restrict__ nsamp_p,
                      float*        __restrict__ out)
{
    const int lane = threadIdx.x & 31;
    const int warp = threadIdx.x >> 5;
    const int b    = blockIdx.x * WARPS_PER_CTA + warp;
    const int g    = lane >> 3;        // group 0..3 (which row of the quad)
    const int t    = lane & 7;         // lane within group

    const float4* __restrict__ f4 = reinterpret_cast<const float4*>(feats);

    // ---- center row: this lane's 16-float column slice ----
    const int node = nodes[b];
    float4 c[4];
    #pragma unroll
    for (int j = 0; j < 4; j++)
        c[j] = f4[(size_t)node * (D_FEAT / 4) + t + 8 * j];

    // ---- my neighbor index (one coalesced 128B load) ----
    const int my_idx = neighs[b * K_NEIGH + lane];

    // ---- similarities: 8 passes x 4 rows; lane 8g+p keeps sim of row 4p+g ----
    float my_sim = 0.0f;
    #pragma unroll
    for (int p = 0; p < K_NEIGH / 4; p++) {
        const int nidx = __shfl_sync(0xffffffffu, my_idx, 4 * p + g);
        const float4* __restrict__ row = f4 + (size_t)nidx * (D_FEAT / 4);

        float dot = 0.0f, ss = 0.0f;
        #pragma unroll
        for (int j = 0; j < 4; j++) {
            const float4 v = row[t + 8 * j];
            dot = fmaf(v.x, c[j].x, fmaf(v.y, c[j].y,
                  fmaf(v.z, c[j].z, fmaf(v.w, c[j].w, dot))));
            ss  = fmaf(v.x, v.x, fmaf(v.y, v.y,
                  fmaf(v.z, v.z, fmaf(v.w, v.w, ss))));
        }
        // 3-stage butterfly within each 8-lane group (serves 4 rows at once)
        #pragma unroll
        for (int off = 1; off < 8; off <<= 1) {
            dot += __shfl_xor_sync(0xffffffffu, dot, off);
            ss  += __shfl_xor_sync(0xffffffffu, ss,  off);
        }
        if (t == p) my_sim = dot * rsqrtf(ss);   // owner lane 8g+p <- row 4p+g
    }

    const int ns = nsamp_p ? *nsamp_p : 10;

    // ---- single-pass rank selection (independent, pipelined shuffles) ----
    int rank = 0;
    #pragma unroll
    for (int j = 0; j < K_NEIGH; j++) {
        const float sj = __shfl_sync(0xffffffffu, my_sim, j);
        rank += (sj > my_sim) | ((sj == my_sim) & (j < lane));
    }
    unsigned wmask = __ballot_sync(0xffffffffu, rank < ns);  // exactly ns bits

    // ---- resolve winner node indices, then batch all gathers (MLP=ns) ----
    float4 acc0 = make_float4(0.f, 0.f, 0.f, 0.f);
    float4 acc1 = make_float4(0.f, 0.f, 0.f, 0.f);
    if (ns == 10) {                       // fast path: fully unrolled batch
        int nn[10];
        unsigned wm = wmask;
        #pragma unroll
        for (int i = 0; i < 10; i++) {
            const int w = __ffs(wm) - 1;
            wm &= wm - 1;
            nn[i] = __shfl_sync(0xffffffffu, my_idx, 4 * (w & 7) + (w >> 3));
        }
        #pragma unroll
        for (int i = 0; i < 10; i++) {
            const float4 v = f4[(size_t)nn[i] * (D_FEAT / 4) + lane];
            if (i & 1) { acc1.x += v.x; acc1.y += v.y; acc1.z += v.z; acc1.w += v.w; }
            else       { acc0.x += v.x; acc0.y += v.y; acc0.z += v.z; acc0.w += v.w; }
        }
    } else {
        int i = 0;
        while (wmask) {
            const int w = __ffs(wmask) - 1;
            wmask &= wmask - 1;
            const int nnid = __shfl_sync(0xffffffffu, my_idx, 4 * (w & 7) + (w >> 3));
            const float4 v = f4[(size_t)nnid * (D_FEAT / 4) + lane];
            if (i & 1) { acc1.x += v.x; acc1.y += v.y; acc1.z += v.z; acc1.w += v.w; }
            else       { acc0.x += v.x; acc0.y += v.y; acc0.z += v.z; acc0.w += v.w; }
            i++;
        }
    }

    // ---- mean + relu, coalesced store ----
    const float inv = 1.0f / (float)ns;
    float4 r;
    r.x = fmaxf((acc0.x + acc1.x) * inv, 0.0f);
    r.y = fmaxf((acc0.y + acc1.y) * inv, 0.0f);
    r.z = fmaxf((acc0.z + acc1.z) * inv, 0.0f);
    r.w = fmaxf((acc0.w + acc1.w) * inv, 0.0f);
    reinterpret_cast<float4*>(out)[(size_t)b * (D_FEAT / 4) + lane] = r;
}

extern "C" void kernel_launch(void* const* d_in, const int* in_sizes, int n_in,
                              void* d_out, int out_size)
{
    const float* feats  = (const float*)d_in[0];   // [N_NODES, 128] f32
    const int*   nodes  = (const int*)d_in[1];     // [B] i32
    const int*   neighs = (const int*)d_in[2];     // [B, 32] i32
    const int*   nsamp  = (n_in > 3) ? (const int*)d_in[3] : nullptr;  // scalar (10)

    const int B = in_sizes[1];                     // 32768
    intra_agg_kernel<<<B / WARPS_PER_CTA, WARPS_PER_CTA * 32>>>(
        feats, nodes, neighs, nsamp, (float*)d_out);
}

// round 16
// speedup vs baseline: 1.1317x; 1.1317x over previous
#include <cuda_runtime.h>
#include <math_constants.h>

#define D_FEAT   128
#define K_NEIGH  32
#define WARPS_PER_CTA 4

// Map float -> uint preserving order (monotone), so integer max == float max.
__device__ __forceinline__ unsigned order_key(float f) {
    unsigned x = __float_as_uint(f);
    return (x & 0x80000000u) ? ~x : (x | 0x80000000u);
}

// FINAL (R9 config — measured optimum at the LTS bandwidth floor).
// One WARP per batch item, no shared memory.
//
// Evidence this is the floor:
//  * sim-phase L2 flow = 32768 items x 16.4 KB = 537 MB in ~82k cycles
//    ~= 6550 B/cyc, at the B300 path-independent LTS cap (~6300 B/cyc);
//    DRAM only ~17% (51.2 MB feature table is L2-resident).
//  * (regs, CTAs/SM) curve: 48/10 -> L2 55%; 56/9 -> 64.4% (this); 80/6 -> 60%.
//  * rejected with measurements: 2-items/warp (R10), smem row stash (R7/R8),
//    rank selection (R4/R13), f32x2 packing (R5), 48-reg trim (R11/12).
//
// Structure:
//  * Sim: 4 rows per pass; warp = 4 groups x 8 lanes, each group owns one row
//    in 128B-contiguous chunks (wavefront-optimal); dot & sumsq reduced by a
//    3-stage butterfly per group (each shuffle serves 4 rows). Owner
//    permutation lane 8g+p <- row 4p+g kills the routing shuffle; exact-sim
//    ties only arise from duplicate neighbor indices (identical rows), so
//    owner-order tie-break is output-equivalent to jax.lax.top_k row-order.
//  * Key = dot * rsqrt(||n||^2): center norm cancels in top-k ordering.
//  * Selection: ns rounds of exact REDUX argmax recorded into a bitmask
//    first; then all ns winner indices resolved and gathers issued
//    back-to-back (MLP=ns, mostly L1/L2-hot) into two accumulator chains.
__global__ __launch_bounds__(WARPS_PER_CTA * 32, 9)
void intra_agg_kernel(const float*  __restrict__ feats,
                      const int*    __restrict__ nodes,
                      const int*    __restrict__ neighs,
                      const int*    __restrict__ nsamp_p,
                      float*        __restrict__ out)
{
    const int lane = threadIdx.x & 31;
    const int warp = threadIdx.x >> 5;
    const int b    = blockIdx.x * WARPS_PER_CTA + warp;
    const int g    = lane >> 3;        // group 0..3 (which row of the quad)
    const int t    = lane & 7;         // lane within group

    const float4* __restrict__ f4 = reinterpret_cast<const float4*>(feats);

    // ---- center row: this lane's 16-float column slice ----
    const int node = nodes[b];
    float4 c[4];
    #pragma unroll
    for (int j = 0; j < 4; j++)
        c[j] = f4[(size_t)node * (D_FEAT / 4) + t + 8 * j];

    // ---- my neighbor index (one coalesced 128B load) ----
    const int my_idx = neighs[b * K_NEIGH + lane];

    // ---- similarities: 8 passes x 4 rows; lane 8g+p keeps sim of row 4p+g ----
    float my_sim = 0.0f;
    #pragma unroll
    for (int p = 0; p < K_NEIGH / 4; p++) {
        const int nidx = __shfl_sync(0xffffffffu, my_idx, 4 * p + g);
        const float4* __restrict__ row = f4 + (size_t)nidx * (D_FEAT / 4);

        float dot = 0.0f, ss = 0.0f;
        #pragma unroll
        for (int j = 0; j < 4; j++) {
            const float4 v = row[t + 8 * j];
            dot = fmaf(v.x, c[j].x, fmaf(v.y, c[j].y,
                  fmaf(v.z, c[j].z, fmaf(v.w, c[j].w, dot))));
            ss  = fmaf(v.x, v.x, fmaf(v.y, v.y,
                  fmaf(v.z, v.z, fmaf(v.w, v.w, ss))));
        }
        // 3-stage butterfly within each 8-lane group (serves 4 rows at once)
        #pragma unroll
        for (int off = 1; off < 8; off <<= 1) {
            dot += __shfl_xor_sync(0xffffffffu, dot, off);
            ss  += __shfl_xor_sync(0xffffffffu, ss,  off);
        }
        if (t == p) my_sim = dot * rsqrtf(ss);   // owner lane 8g+p <- row 4p+g
    }

    const int ns = nsamp_p ? *nsamp_p : 10;

    // ---- top-ns selection: record winner OWNER lanes into a bitmask ----
    unsigned u = order_key(my_sim);
    unsigned wmask = 0u;
    for (int i = 0; i < ns; i++) {
        const unsigned m   = __reduce_max_sync(0xffffffffu, u);
        const unsigned msk = __ballot_sync(0xffffffffu, u == m);
        const int      w   = __ffs(msk) - 1;            // tie -> duplicate row
        if (lane == w) u = 0u;                          // below any real key
        wmask |= 1u << w;
    }

    // ---- resolve winner node indices, then batch all gathers (MLP=ns) ----
    float4 acc0 = make_float4(0.f, 0.f, 0.f, 0.f);
    float4 acc1 = make_float4(0.f, 0.f, 0.f, 0.f);
    if (ns == 10) {                       // fast path: fully unrolled batch
        int nn[10];
        unsigned wm = wmask;
        #pragma unroll
        for (int i = 0; i < 10; i++) {
            const int w = __ffs(wm) - 1;
            wm &= wm - 1;
            const int r = 4 * (w & 7) + (w >> 3);       // owner lane -> row
            nn[i] = __shfl_sync(0xffffffffu, my_idx, r);
        }
        #pragma unroll
        for (int i = 0; i < 10; i++) {
            const float4 v = f4[(size_t)nn[i] * (D_FEAT / 4) + lane];
            if (i & 1) { acc1.x += v.x; acc1.y += v.y; acc1.z += v.z; acc1.w += v.w; }
            else       { acc0.x += v.x; acc0.y += v.y; acc0.z += v.z; acc0.w += v.w; }
        }
    } else {
        int i = 0;
        while (wmask) {
            const int w = __ffs(wmask) - 1;
            wmask &= wmask - 1;
            const int r = 4 * (w & 7) + (w >> 3);
            const int nnid = __shfl_sync(0xffffffffu, my_idx, r);
            const float4 v = f4[(size_t)nnid * (D_FEAT / 4) + lane];
            if (i & 1) { acc1.x += v.x; acc1.y += v.y; acc1.z += v.z; acc1.w += v.w; }
            else       { acc0.x += v.x; acc0.y += v.y; acc0.z += v.z; acc0.w += v.w; }
            i++;
        }
    }

    // ---- mean + relu, coalesced store ----
    const float inv = 1.0f / (float)ns;
    float4 r;
    r.x = fmaxf((acc0.x + acc1.x) * inv, 0.0f);
    r.y = fmaxf((acc0.y + acc1.y) * inv, 0.0f);
    r.z = fmaxf((acc0.z + acc1.z) * inv, 0.0f);
    r.w = fmaxf((acc0.w + acc1.w) * inv, 0.0f);
    reinterpret_cast<float4*>(out)[(size_t)b * (D_FEAT / 4) + lane] = r;
}

extern "C" void kernel_launch(void* const* d_in, const int* in_sizes, int n_in,
                              void* d_out, int out_size)
{
    const float* feats  = (const float*)d_in[0];   // [N_NODES, 128] f32
    const int*   nodes  = (const int*)d_in[1];     // [B] i32
    const int*   neighs = (const int*)d_in[2];     // [B, 32] i32
    const int*   nsamp  = (n_in > 3) ? (const int*)d_in[3] : nullptr;  // scalar (10)

    const int B = in_sizes[1];                     // 32768
    intra_agg_kernel<<<B / WARPS_PER_CTA, WARPS_PER_CTA * 32>>>(
        feats, nodes, neighs, nsamp, (float*)d_out);
}